// round 2
// baseline (speedup 1.0000x reference)
#include <cuda_runtime.h>

// ---------------------------------------------------------------------------
// AFNO2D: rfft2(128x128, ortho) -> blockwise complex MLP (8 blocks x 96ch,
// relu, softshrink 0.01) -> irfft2 -> + x.
// Pipeline: K1 rfftW  x->A ; K2 fftH A->B (*1/128) ; K3 MLP B->A ;
//           K4 ifftH A->B ; K5 irfftW B (+x, *1/128) -> out
// ---------------------------------------------------------------------------

#define BB 4
#define HH 128
#define WW 128
#define CH 768
#define NB 8
#define BS 96
#define WF 65
#define MPTS (BB*HH*WF)   /* 33280 frequency points */

// scratch (device globals: allocation-free)
__device__ float2 g_A[(size_t)MPTS * CH];
__device__ float2 g_B[(size_t)MPTS * CH];

typedef unsigned long long u64;

__device__ __forceinline__ int brev7(int j) { return (int)(__brev((unsigned)j) >> 25); }

__device__ __forceinline__ u64 pk2(float a, float b) {
    u64 r; asm("mov.b64 %0,{%1,%2};" : "=l"(r) : "f"(a), "f"(b)); return r;
}
__device__ __forceinline__ void unpk2(u64 v, float& a, float& b) {
    asm("mov.b64 {%0,%1},%2;" : "=f"(a), "=f"(b) : "l"(v));
}
__device__ __forceinline__ u64 ffma2(u64 a, u64 b, u64 c) {
    u64 d; asm("fma.rn.f32x2 %0,%1,%2,%3;" : "=l"(d) : "l"(a), "l"(b), "l"(c)); return d;
}

// ---------------------------------------------------------------------------
// per-thread iterative radix-2 FFT, N=128, data in smem row (stride 1),
// twiddles twc[j]=cos(2pi j/128), tws[j]=sin(2pi j/128); dir=-1 fwd, +1 inv.
// Input must be placed in bit-reversed order.
// ---------------------------------------------------------------------------
__device__ __forceinline__ void fft128(float* re, float* im,
                                       const float* twc, const float* tws, float dir)
{
    #pragma unroll
    for (int s = 1; s <= 7; s++) {
        const int half  = 1 << (s - 1);
        const int tstep = 128 >> s;
        for (int j0 = 0; j0 < 128; j0 += (half << 1)) {
            for (int j = 0; j < half; j++) {
                float wr = twc[j * tstep];
                float wi = dir * tws[j * tstep];
                int a = j0 + j, b = a + half;
                float br = re[b], bi = im[b];
                float tr = br * wr - bi * wi;
                float ti = br * wi + bi * wr;
                float ar = re[a], ai = im[a];
                re[b] = ar - tr; im[b] = ai - ti;
                re[a] = ar + tr; im[a] = ai + ti;
            }
        }
    }
}

#define FFT_PITCH 129

// ---------------- K1: rfft along W: x -> g_A[b,h,wf,c] ---------------------
__global__ void k1_rfft_w(const float* __restrict__ x)
{
    __shared__ float sre[32 * FFT_PITCH], sim[32 * FFT_PITCH];
    __shared__ float twc[64], tws[64];
    int t = threadIdx.x;
    for (int j = t; j < 64; j += 32) {
        float s, c; sincospif(j * (1.0f / 64.0f), &s, &c);
        twc[j] = c; tws[j] = s;
    }
    int bh = blockIdx.y;                 // b*128+h
    int c0 = blockIdx.x * 32 + t;
    float* re = &sre[t * FFT_PITCH];
    float* im = &sim[t * FFT_PITCH];

    const float* px = x + (size_t)bh * WW * CH + c0;
    for (int w = 0; w < 128; w++) re[brev7(w)] = px[(size_t)w * CH];
    for (int w = 0; w < 128; w++) im[w] = 0.0f;
    __syncthreads();

    fft128(re, im, twc, tws, -1.0f);

    float2* pa = g_A + (size_t)bh * WF * CH + c0;
    for (int k = 0; k <= 64; k++) pa[(size_t)k * CH] = make_float2(re[k], im[k]);
}

// ---------------- K2: fft along H: g_A -> g_B, scale 1/128 -----------------
__global__ void k2_fft_h()
{
    __shared__ float sre[32 * FFT_PITCH], sim[32 * FFT_PITCH];
    __shared__ float twc[64], tws[64];
    int t = threadIdx.x;
    for (int j = t; j < 64; j += 32) {
        float s, c; sincospif(j * (1.0f / 64.0f), &s, &c);
        twc[j] = c; tws[j] = s;
    }
    int bwf = blockIdx.y;               // b*65 + wf
    int b  = bwf / WF;
    int wf = bwf - b * WF;
    int c0 = blockIdx.x * 32 + t;
    float* re = &sre[t * FFT_PITCH];
    float* im = &sim[t * FFT_PITCH];

    const float2* pa = g_A + ((size_t)b * HH * WF + wf) * CH + c0;
    for (int h = 0; h < 128; h++) {
        float2 v = pa[(size_t)h * WF * CH];
        int p = brev7(h);
        re[p] = v.x; im[p] = v.y;
    }
    __syncthreads();

    fft128(re, im, twc, tws, -1.0f);

    float2* pb = g_B + ((size_t)b * HH * WF + wf) * CH + c0;
    const float sc = 1.0f / 128.0f;
    for (int h = 0; h < 128; h++)
        pb[(size_t)h * WF * CH] = make_float2(re[h] * sc, im[h] * sc);
}

// ---------------- K3: blockwise complex MLP: g_B -> g_A --------------------
// block = (channel-block n, tile of 32 freq points); 96 threads (one per out ch)
__global__ void __launch_bounds__(96) k3_mlp(const float* __restrict__ w1,
                                             const float* __restrict__ b1,
                                             const float* __restrict__ w2,
                                             const float* __restrict__ b2)
{
    __shared__ float2 sx[32][BS];
    const int o  = threadIdx.x;           // 0..95
    const int n  = blockIdx.x;            // 0..7
    const int m0 = blockIdx.y * 32;

    // load x tile (rows are contiguous rows of g_B)
    for (int idx = o; idx < 32 * BS; idx += BS) {
        int p = idx / BS, i = idx - p * BS;
        sx[p][i] = g_B[(size_t)(m0 + p) * CH + n * BS + i];
    }
    __syncthreads();

    // ---- layer 1: o1 = relu(x W1 + b1), complex (W = w1[0] + i w1[1]) -----
    const float* w1r = w1 + (size_t)n * BS * BS;
    const float* w1i = w1 + (size_t)(NB + n) * BS * BS;
    u64 acc[32];
    {
        float bre = b1[n * BS + o];
        float bim = b1[NB * BS + n * BS + o];
        u64 binit = pk2(bre, bim);
        #pragma unroll
        for (int p = 0; p < 32; p++) acc[p] = binit;
    }
    for (int i = 0; i < BS; i++) {
        float wr = w1r[i * BS + o];
        float wi = w1i[i * BS + o];
        u64 wri = pk2(wr, wi);
        u64 wir = pk2(-wi, wr);
        #pragma unroll
        for (int p = 0; p < 32; p++) {
            float2 xv = sx[p][i];
            acc[p] = ffma2(pk2(xv.x, xv.x), wri, acc[p]);
            acc[p] = ffma2(pk2(xv.y, xv.y), wir, acc[p]);
        }
    }
    __syncthreads();
    #pragma unroll
    for (int p = 0; p < 32; p++) {
        float r, ii; unpk2(acc[p], r, ii);
        sx[p][o] = make_float2(fmaxf(r, 0.0f), fmaxf(ii, 0.0f));
    }
    __syncthreads();

    // ---- layer 2: o2 = o1 W2 + b2, softshrink --------------------------
    const float* w2r = w2 + (size_t)n * BS * BS;
    const float* w2i = w2 + (size_t)(NB + n) * BS * BS;
    {
        float bre = b2[n * BS + o];
        float bim = b2[NB * BS + n * BS + o];
        u64 binit = pk2(bre, bim);
        #pragma unroll
        for (int p = 0; p < 32; p++) acc[p] = binit;
    }
    for (int i = 0; i < BS; i++) {
        float wr = w2r[i * BS + o];
        float wi = w2i[i * BS + o];
        u64 wri = pk2(wr, wi);
        u64 wir = pk2(-wi, wr);
        #pragma unroll
        for (int p = 0; p < 32; p++) {
            float2 xv = sx[p][i];
            acc[p] = ffma2(pk2(xv.x, xv.x), wri, acc[p]);
            acc[p] = ffma2(pk2(xv.y, xv.y), wir, acc[p]);
        }
    }
    const float lam = 0.01f;
    #pragma unroll
    for (int p = 0; p < 32; p++) {
        float r, ii; unpk2(acc[p], r, ii);
        r  = copysignf(fmaxf(fabsf(r)  - lam, 0.0f), r);
        ii = copysignf(fmaxf(fabsf(ii) - lam, 0.0f), ii);
        g_A[(size_t)(m0 + p) * CH + n * BS + o] = make_float2(r, ii);
    }
}

// ---------------- K4: inverse fft along H: g_A -> g_B ----------------------
__global__ void k4_ifft_h()
{
    __shared__ float sre[32 * FFT_PITCH], sim[32 * FFT_PITCH];
    __shared__ float twc[64], tws[64];
    int t = threadIdx.x;
    for (int j = t; j < 64; j += 32) {
        float s, c; sincospif(j * (1.0f / 64.0f), &s, &c);
        twc[j] = c; tws[j] = s;
    }
    int bwf = blockIdx.y;
    int b  = bwf / WF;
    int wf = bwf - b * WF;
    int c0 = blockIdx.x * 32 + t;
    float* re = &sre[t * FFT_PITCH];
    float* im = &sim[t * FFT_PITCH];

    const float2* pa = g_A + ((size_t)b * HH * WF + wf) * CH + c0;
    for (int h = 0; h < 128; h++) {
        float2 v = pa[(size_t)h * WF * CH];
        int p = brev7(h);
        re[p] = v.x; im[p] = v.y;
    }
    __syncthreads();

    fft128(re, im, twc, tws, +1.0f);

    float2* pb = g_B + ((size_t)b * HH * WF + wf) * CH + c0;
    for (int h = 0; h < 128; h++)
        pb[(size_t)h * WF * CH] = make_float2(re[h], im[h]);
}

// ---------- K5: inverse rfft along W (+ residual, *1/128): g_B,x -> out ----
__global__ void k5_irfft_w(const float* __restrict__ x, float* __restrict__ out)
{
    __shared__ float sre[32 * FFT_PITCH], sim[32 * FFT_PITCH];
    __shared__ float twc[64], tws[64];
    int t = threadIdx.x;
    for (int j = t; j < 64; j += 32) {
        float s, c; sincospif(j * (1.0f / 64.0f), &s, &c);
        twc[j] = c; tws[j] = s;
    }
    int bh = blockIdx.y;
    int c0 = blockIdx.x * 32 + t;
    float* re = &sre[t * FFT_PITCH];
    float* im = &sim[t * FFT_PITCH];

    const float2* pb = g_B + (size_t)bh * WF * CH + c0;
    for (int k = 0; k <= 64; k++) {
        float2 v = pb[(size_t)k * CH];
        int p = brev7(k);
        re[p] = v.x; im[p] = v.y;
        if (k >= 1 && k <= 63) {        // Hermitian completion
            int q = brev7(128 - k);
            re[q] = v.x; im[q] = -v.y;
        }
    }
    __syncthreads();

    fft128(re, im, twc, tws, +1.0f);

    const float* px = x   + (size_t)bh * WW * CH + c0;
    float*       po = out + (size_t)bh * WW * CH + c0;
    const float sc = 1.0f / 128.0f;
    for (int w = 0; w < 128; w++)
        po[(size_t)w * CH] = fmaf(re[w], sc, px[(size_t)w * CH]);
}

// ---------------------------------------------------------------------------
extern "C" void kernel_launch(void* const* d_in, const int* in_sizes, int n_in,
                              void* d_out, int out_size)
{
    (void)in_sizes; (void)n_in; (void)out_size;
    const float* x  = (const float*)d_in[0];
    const float* w1 = (const float*)d_in[1];
    const float* b1 = (const float*)d_in[2];
    const float* w2 = (const float*)d_in[3];
    const float* b2 = (const float*)d_in[4];
    float* out = (float*)d_out;

    k1_rfft_w <<<dim3(CH / 32, BB * HH), 32>>>(x);
    k2_fft_h  <<<dim3(CH / 32, BB * WF), 32>>>();
    k3_mlp    <<<dim3(NB, MPTS / 32), 96>>>(w1, b1, w2, b2);
    k4_ifft_h <<<dim3(CH / 32, BB * WF), 32>>>();
    k5_irfft_w<<<dim3(CH / 32, BB * HH), 32>>>(x, out);
}

// round 3
// speedup vs baseline: 2.8029x; 2.8029x over previous
#include <cuda_runtime.h>
#include <cuda_bf16.h>

// ---------------------------------------------------------------------------
// AFNO2D: rfft2(128x128, ortho) -> blockwise complex MLP (8 blocks x 96ch,
// relu, softshrink 0.01) -> irfft2 -> + x.
// K1 rfftW x->A ; K2 fftH A->B (*1/128) ; K3 MLP (bf16 tensor cores) B->A ;
// K4 ifftH A->B ; K5 irfftW B (+x, *1/128) -> out
// ---------------------------------------------------------------------------

#define BB 4
#define HH 128
#define WW 128
#define CH 768
#define NB 8
#define BS 96
#define WF 65
#define MPTS (BB*HH*WF)   /* 33280 frequency points */

__device__ float2 g_A[(size_t)MPTS * CH];
__device__ float2 g_B[(size_t)MPTS * CH];

__device__ __forceinline__ int brev7(int j) { return (int)(__brev((unsigned)j) >> 25); }

// ---------------------------------------------------------------------------
// 128-pt FFT on a thread-private smem row of float2. Input bit-reversed,
// output natural order. Stage 1 radix-2 (tw=1) + 3 fused radix-4 stages.
// tw[k] = (cos(2pi k/128), sin(2pi k/128)); dir=-1 fwd, +1 inv.
// ---------------------------------------------------------------------------
__device__ __forceinline__ void fft128_f2(float2* d, const float2* tw, float dir)
{
    // stage 1: half=1, twiddle = 1
    for (int j0 = 0; j0 < 128; j0 += 2) {
        float2 a = d[j0], b = d[j0 + 1];
        d[j0]     = make_float2(a.x + b.x, a.y + b.y);
        d[j0 + 1] = make_float2(a.x - b.x, a.y - b.y);
    }
    // fused radix-4 stages: h = 2, 8, 32 (covers radix-2 halves (2,4),(8,16),(32,64))
    #pragma unroll
    for (int s = 0; s < 3; s++) {
        const int h  = 2 << (2 * s);
        const int M1 = 64 / h;     // stage-s twiddle step
        const int M2 = 32 / h;     // stage-(s+1) twiddle step
        for (int j = 0; j < h; j++) {
            float2 t1 = tw[j * M1];
            float2 t2 = tw[j * M2];
            float w1r = t1.x, w1i = dir * t1.y;
            float w2r = t2.x, w2i = dir * t2.y;
            float w3r = -t2.y, w3i = dir * t2.x;   // w2 * (dir * i) => W^(jM2+32)
            for (int g4 = j; g4 < 128; g4 += 4 * h) {
                int i0 = g4, i1 = g4 + h, i2 = g4 + 2 * h, i3 = g4 + 3 * h;
                float2 x0 = d[i0], x1 = d[i1], x2 = d[i2], x3 = d[i3];
                float t1r = x1.x * w1r - x1.y * w1i, t1i = x1.x * w1i + x1.y * w1r;
                float t3r = x3.x * w1r - x3.y * w1i, t3i = x3.x * w1i + x3.y * w1r;
                float u0r = x0.x + t1r, u0i = x0.y + t1i;
                float u1r = x0.x - t1r, u1i = x0.y - t1i;
                float u2r = x2.x + t3r, u2i = x2.y + t3i;
                float u3r = x2.x - t3r, u3i = x2.y - t3i;
                float a2r = u2r * w2r - u2i * w2i, a2i = u2r * w2i + u2i * w2r;
                float a3r = u3r * w3r - u3i * w3i, a3i = u3r * w3i + u3i * w3r;
                d[i0] = make_float2(u0r + a2r, u0i + a2i);
                d[i2] = make_float2(u0r - a2r, u0i - a2i);
                d[i1] = make_float2(u1r + a3r, u1i + a3i);
                d[i3] = make_float2(u1r - a3r, u1i - a3i);
            }
        }
    }
}

#define FP2 129   /* float2 pitch per line: 2 lanes 16 apart land on distinct banks */

__device__ __forceinline__ void build_tw(float2* tw, int t)
{
    for (int j = t; j < 64; j += 32) {
        float s, c; sincospif(j * (1.0f / 64.0f), &s, &c);
        tw[j] = make_float2(c, s);
    }
}

// ---------------- K1: rfft along W: x -> g_A[b,h,wf,c] ---------------------
__global__ void k1_rfft_w(const float* __restrict__ x)
{
    __shared__ float2 sd[32 * FP2];
    __shared__ float2 tw[64];
    int t = threadIdx.x;
    build_tw(tw, t);
    int bh = blockIdx.y;
    int c0 = blockIdx.x * 32 + t;
    float2* d = &sd[t * FP2];

    const float* px = x + (size_t)bh * WW * CH + c0;
    for (int w = 0; w < 128; w++) d[brev7(w)] = make_float2(px[(size_t)w * CH], 0.0f);
    __syncthreads();

    fft128_f2(d, tw, -1.0f);

    float2* pa = g_A + (size_t)bh * WF * CH + c0;
    for (int k = 0; k <= 64; k++) pa[(size_t)k * CH] = d[k];
}

// ---------------- K2: fft along H: g_A -> g_B, scale 1/128 -----------------
__global__ void k2_fft_h()
{
    __shared__ float2 sd[32 * FP2];
    __shared__ float2 tw[64];
    int t = threadIdx.x;
    build_tw(tw, t);
    int bwf = blockIdx.y;
    int b = bwf / WF, wf = bwf - b * WF;
    int c0 = blockIdx.x * 32 + t;
    float2* d = &sd[t * FP2];

    const float2* pa = g_A + ((size_t)b * HH * WF + wf) * CH + c0;
    for (int h = 0; h < 128; h++) d[brev7(h)] = pa[(size_t)h * WF * CH];
    __syncthreads();

    fft128_f2(d, tw, -1.0f);

    float2* pb = g_B + ((size_t)b * HH * WF + wf) * CH + c0;
    const float sc = 1.0f / 128.0f;
    for (int h = 0; h < 128; h++)
        pb[(size_t)h * WF * CH] = make_float2(d[h].x * sc, d[h].y * sc);
}

// ---------------------------------------------------------------------------
// K3: blockwise complex MLP on tensor cores (bf16 mma.sync, fp32 accum).
// Per CTA: channel block n, 128 points. X~=[xr|xi] (128x192 bf16), layers as
// 4 sign-combined K=96 GEMMs. 8 warps = 4(M) x 2(N-half: re/im outputs).
// ---------------------------------------------------------------------------
#define XP 200    /* sX pitch in bf16  */
#define WP 104    /* sW pitch in bf16  */
#define SP 200    /* stage pitch fp32  */
#define SM_X   0
#define SM_WR  51200
#define SM_WI  71168
#define SM_B1  102400
#define SM_B2  103168
#define SM_K3  103936

__device__ __forceinline__ void mma_bf16(float* d, const unsigned* a, unsigned b0, unsigned b1)
{
    asm volatile(
        "mma.sync.aligned.m16n8k16.row.col.f32.bf16.bf16.f32 "
        "{%0,%1,%2,%3},{%4,%5,%6,%7},{%8,%9},{%0,%1,%2,%3};"
        : "+f"(d[0]), "+f"(d[1]), "+f"(d[2]), "+f"(d[3])
        : "r"(a[0]), "r"(a[1]), "r"(a[2]), "r"(a[3]), "r"(b0), "r"(b1));
}

__global__ void __launch_bounds__(256) k3_mlp(const float* __restrict__ w1,
                                              const float* __restrict__ b1,
                                              const float* __restrict__ w2,
                                              const float* __restrict__ b2)
{
    extern __shared__ char sm[];
    __nv_bfloat16* sX  = (__nv_bfloat16*)(sm + SM_X);
    __nv_bfloat16* sWr = (__nv_bfloat16*)(sm + SM_WR);
    __nv_bfloat16* sWi = (__nv_bfloat16*)(sm + SM_WI);
    float* stage = (float*)(sm + SM_X);
    float* sB1   = (float*)(sm + SM_B1);
    float* sB2   = (float*)(sm + SM_B2);

    const int tid = threadIdx.x;
    const int n   = blockIdx.x;
    const int m0  = blockIdx.y * 128;
    const int lane = tid & 31, warp = tid >> 5;
    const int g = lane >> 2, tig = lane & 3;
    const int wm = warp & 3, wn = warp >> 2;

    // load X tile: [m][0:96)=re, [96:192)=im
    for (int idx = tid; idx < 128 * 96; idx += 256) {
        int m = idx / 96, i = idx - (idx / 96) * 96;
        float2 v = g_B[(size_t)(m0 + m) * CH + n * BS + i];
        sX[m * XP + i]      = __float2bfloat16_rn(v.x);
        sX[m * XP + 96 + i] = __float2bfloat16_rn(v.y);
    }
    // load W1 (transposed to [o][i]) and biases
    {
        const float* wr = w1 + (size_t)n * BS * BS;
        const float* wi = w1 + (size_t)(NB + n) * BS * BS;
        for (int idx = tid; idx < BS * BS; idx += 256) {
            int i = idx / 96, o = idx - (idx / 96) * 96;
            sWr[o * WP + i] = __float2bfloat16_rn(wr[idx]);
            sWi[o * WP + i] = __float2bfloat16_rn(wi[idx]);
        }
        if (tid < 192) {
            int half = tid / 96, j = tid - half * 96;
            sB1[tid] = b1[half * (NB * BS) + n * BS + j];
            sB2[tid] = b2[half * (NB * BS) + n * BS + j];
        }
    }
    __syncthreads();

    float acc[2][12][4];

    // ======================= layer 1 =======================
    #pragma unroll
    for (int mt = 0; mt < 2; mt++)
        #pragma unroll
        for (int nt = 0; nt < 12; nt++)
            #pragma unroll
            for (int r = 0; r < 4; r++) acc[mt][nt][r] = 0.0f;

    for (int ks = 0; ks < 12; ks++) {
        int khalf = (ks >= 6);
        int k0 = ks * 16, kk = k0 - khalf * 96;
        const __nv_bfloat16* sW = (wn == 0) ? (khalf ? sWi : sWr)
                                            : (khalf ? sWr : sWi);
        bool negA = (wn == 0) && khalf;

        unsigned a[2][4];
        #pragma unroll
        for (int mt = 0; mt < 2; mt++) {
            const __nv_bfloat16* ap = sX + (wm * 32 + mt * 16 + g) * XP + k0 + 2 * tig;
            a[mt][0] = *(const unsigned*)(ap);
            a[mt][1] = *(const unsigned*)(ap + 8 * XP);
            a[mt][2] = *(const unsigned*)(ap + 8);
            a[mt][3] = *(const unsigned*)(ap + 8 * XP + 8);
        }
        if (negA) {
            #pragma unroll
            for (int mt = 0; mt < 2; mt++)
                #pragma unroll
                for (int r = 0; r < 4; r++) a[mt][r] ^= 0x80008000u;
        }
        #pragma unroll
        for (int nt = 0; nt < 12; nt++) {
            const __nv_bfloat16* bp = sW + (nt * 8 + g) * WP + kk + 2 * tig;
            unsigned b0 = *(const unsigned*)(bp);
            unsigned b1v = *(const unsigned*)(bp + 8);
            mma_bf16(acc[0][nt], a[0], b0, b1v);
            mma_bf16(acc[1][nt], a[1], b0, b1v);
        }
    }
    __syncthreads();   // all reads of sX / sW done

    // epilogue L1: +bias, relu, bf16 -> sX (Y1); load W2 into sW
    #pragma unroll
    for (int mt = 0; mt < 2; mt++) {
        #pragma unroll
        for (int nt = 0; nt < 12; nt++) {
            int row0 = wm * 32 + mt * 16 + g;
            int j = wn * 96 + nt * 8 + 2 * tig;
            float bb0 = sB1[j], bb1 = sB1[j + 1];
            __nv_bfloat162 p0 = __floats2bfloat162_rn(
                fmaxf(acc[mt][nt][0] + bb0, 0.0f), fmaxf(acc[mt][nt][1] + bb1, 0.0f));
            __nv_bfloat162 p1 = __floats2bfloat162_rn(
                fmaxf(acc[mt][nt][2] + bb0, 0.0f), fmaxf(acc[mt][nt][3] + bb1, 0.0f));
            *(__nv_bfloat162*)(sX + row0 * XP + j)       = p0;
            *(__nv_bfloat162*)(sX + (row0 + 8) * XP + j) = p1;
        }
    }
    {
        const float* wr = w2 + (size_t)n * BS * BS;
        const float* wi = w2 + (size_t)(NB + n) * BS * BS;
        for (int idx = tid; idx < BS * BS; idx += 256) {
            int i = idx / 96, o = idx - (idx / 96) * 96;
            sWr[o * WP + i] = __float2bfloat16_rn(wr[idx]);
            sWi[o * WP + i] = __float2bfloat16_rn(wi[idx]);
        }
    }
    __syncthreads();

    // ======================= layer 2 =======================
    #pragma unroll
    for (int mt = 0; mt < 2; mt++)
        #pragma unroll
        for (int nt = 0; nt < 12; nt++)
            #pragma unroll
            for (int r = 0; r < 4; r++) acc[mt][nt][r] = 0.0f;

    for (int ks = 0; ks < 12; ks++) {
        int khalf = (ks >= 6);
        int k0 = ks * 16, kk = k0 - khalf * 96;
        const __nv_bfloat16* sW = (wn == 0) ? (khalf ? sWi : sWr)
                                            : (khalf ? sWr : sWi);
        bool negA = (wn == 0) && khalf;

        unsigned a[2][4];
        #pragma unroll
        for (int mt = 0; mt < 2; mt++) {
            const __nv_bfloat16* ap = sX + (wm * 32 + mt * 16 + g) * XP + k0 + 2 * tig;
            a[mt][0] = *(const unsigned*)(ap);
            a[mt][1] = *(const unsigned*)(ap + 8 * XP);
            a[mt][2] = *(const unsigned*)(ap + 8);
            a[mt][3] = *(const unsigned*)(ap + 8 * XP + 8);
        }
        if (negA) {
            #pragma unroll
            for (int mt = 0; mt < 2; mt++)
                #pragma unroll
                for (int r = 0; r < 4; r++) a[mt][r] ^= 0x80008000u;
        }
        #pragma unroll
        for (int nt = 0; nt < 12; nt++) {
            const __nv_bfloat16* bp = sW + (nt * 8 + g) * WP + kk + 2 * tig;
            unsigned b0 = *(const unsigned*)(bp);
            unsigned b1v = *(const unsigned*)(bp + 8);
            mma_bf16(acc[0][nt], a[0], b0, b1v);
            mma_bf16(acc[1][nt], a[1], b0, b1v);
        }
    }
    __syncthreads();   // sX/sW reads done; stage aliases them

    // epilogue L2: +bias -> fp32 stage
    #pragma unroll
    for (int mt = 0; mt < 2; mt++) {
        #pragma unroll
        for (int nt = 0; nt < 12; nt++) {
            int row0 = wm * 32 + mt * 16 + g;
            int j = wn * 96 + nt * 8 + 2 * tig;
            float bb0 = sB2[j], bb1 = sB2[j + 1];
            *(float2*)&stage[row0 * SP + j] =
                make_float2(acc[mt][nt][0] + bb0, acc[mt][nt][1] + bb1);
            *(float2*)&stage[(row0 + 8) * SP + j] =
                make_float2(acc[mt][nt][2] + bb0, acc[mt][nt][3] + bb1);
        }
    }
    __syncthreads();

    // softshrink + interleaved write to g_A
    const float lam = 0.01f;
    for (int idx = tid; idx < 128 * 96; idx += 256) {
        int m = idx / 96, o = idx - (idx / 96) * 96;
        float r  = stage[m * SP + o];
        float ii = stage[m * SP + 96 + o];
        r  = copysignf(fmaxf(fabsf(r)  - lam, 0.0f), r);
        ii = copysignf(fmaxf(fabsf(ii) - lam, 0.0f), ii);
        g_A[(size_t)(m0 + m) * CH + n * BS + o] = make_float2(r, ii);
    }
}

// ---------------- K4: inverse fft along H: g_A -> g_B ----------------------
__global__ void k4_ifft_h()
{
    __shared__ float2 sd[32 * FP2];
    __shared__ float2 tw[64];
    int t = threadIdx.x;
    build_tw(tw, t);
    int bwf = blockIdx.y;
    int b = bwf / WF, wf = bwf - b * WF;
    int c0 = blockIdx.x * 32 + t;
    float2* d = &sd[t * FP2];

    const float2* pa = g_A + ((size_t)b * HH * WF + wf) * CH + c0;
    for (int h = 0; h < 128; h++) d[brev7(h)] = pa[(size_t)h * WF * CH];
    __syncthreads();

    fft128_f2(d, tw, +1.0f);

    float2* pb = g_B + ((size_t)b * HH * WF + wf) * CH + c0;
    for (int h = 0; h < 128; h++) pb[(size_t)h * WF * CH] = d[h];
}

// ---------- K5: inverse rfft along W (+ residual, *1/128): g_B,x -> out ----
__global__ void k5_irfft_w(const float* __restrict__ x, float* __restrict__ out)
{
    __shared__ float2 sd[32 * FP2];
    __shared__ float2 tw[64];
    int t = threadIdx.x;
    build_tw(tw, t);
    int bh = blockIdx.y;
    int c0 = blockIdx.x * 32 + t;
    float2* d = &sd[t * FP2];

    const float2* pb = g_B + (size_t)bh * WF * CH + c0;
    for (int k = 0; k <= 64; k++) {
        float2 v = pb[(size_t)k * CH];
        d[brev7(k)] = v;
        if (k >= 1 && k <= 63)
            d[brev7(128 - k)] = make_float2(v.x, -v.y);   // Hermitian completion
    }
    __syncthreads();

    fft128_f2(d, tw, +1.0f);

    const float* px = x   + (size_t)bh * WW * CH + c0;
    float*       po = out + (size_t)bh * WW * CH + c0;
    const float sc = 1.0f / 128.0f;
    for (int w = 0; w < 128; w++)
        po[(size_t)w * CH] = fmaf(d[w].x, sc, px[(size_t)w * CH]);
}

// ---------------------------------------------------------------------------
extern "C" void kernel_launch(void* const* d_in, const int* in_sizes, int n_in,
                              void* d_out, int out_size)
{
    (void)in_sizes; (void)n_in; (void)out_size;
    const float* x  = (const float*)d_in[0];
    const float* w1 = (const float*)d_in[1];
    const float* b1 = (const float*)d_in[2];
    const float* w2 = (const float*)d_in[3];
    const float* b2 = (const float*)d_in[4];
    float* out = (float*)d_out;

    cudaFuncSetAttribute(k3_mlp, cudaFuncAttributeMaxDynamicSharedMemorySize, SM_K3);

    k1_rfft_w <<<dim3(CH / 32, BB * HH), 32>>>(x);
    k2_fft_h  <<<dim3(CH / 32, BB * WF), 32>>>();
    k3_mlp    <<<dim3(NB, MPTS / 128), 256, SM_K3>>>(w1, b1, w2, b2);
    k4_ifft_h <<<dim3(CH / 32, BB * WF), 32>>>();
    k5_irfft_w<<<dim3(CH / 32, BB * HH), 32>>>(x, out);
}